// round 2
// baseline (speedup 1.0000x reference)
#include <cuda_runtime.h>
#include <cuda_bf16.h>

// GroupConv2D: B=32, H=W=56, Cin=Cout=256, G=8, 3x3 SAME, NHWC, HWIO weights, fp32.
// d_in[0] = inputs  [32,56,56,256] f32
// d_in[1] = kernel  [3,3,32,256]   f32  (HWIO, I = Cin/G = 32, O spans all 256)
// d_in[2] = bias    [256]          f32
// d_out   = output  [32,56,56,256] f32

namespace {
constexpr int B  = 32;
constexpr int H  = 56;
constexpr int W  = 56;
constexpr int C  = 256;   // Cin == Cout
constexpr int G  = 8;
constexpr int CG = C / G; // 32 channels per group
constexpr int TW = 14;    // output pixels per block along W
constexpr int TILES_W = W / TW;            // 4
constexpr int SCOLS = TW + 2;              // 16 (with halo)
constexpr int SROW  = SCOLS * C;           // 4096 floats per smem row
}

__global__ __launch_bounds__(256, 4)
void groupconv2d_kernel(const float* __restrict__ in,
                        const float* __restrict__ wgt,
                        const float* __restrict__ bias,
                        float* __restrict__ out)
{
    __shared__ float smem[3 * SCOLS * C];  // 48 KB: 3 input rows x 16 cols x 256 ch

    const int tile = blockIdx.x;
    const int tw = tile % TILES_W;
    const int h  = (tile / TILES_W) % H;
    const int b  = tile / (TILES_W * H);
    const int w0 = tw * TW;

    const int co = threadIdx.x;       // output channel 0..255
    const int g  = co >> 5;           // group; warp-uniform (warps align with groups)

    // ---- Stage input tile (rows h-1..h+1, cols w0-1..w0+14, all 256 channels) ----
    // 12288 floats = 3072 float4; 256 threads -> 12 float4 each. Zero-fill halo.
    for (int i = threadIdx.x; i < 3 * SCOLS * C / 4; i += 256) {
        const int idx = i * 4;
        const int ch4 = idx & (C - 1);          // channel offset (multiple of 4)
        const int col = (idx >> 8) & (SCOLS - 1);
        const int row = idx / SROW;
        const int hh = h + row - 1;
        const int ww = w0 + col - 1;
        float4 v = make_float4(0.f, 0.f, 0.f, 0.f);
        if (hh >= 0 && hh < H && ww >= 0 && ww < W) {
            v = *reinterpret_cast<const float4*>(
                    &in[(((long)b * H + hh) * W + ww) * C + ch4]);
        }
        reinterpret_cast<float4*>(smem)[i] = v;
    }
    __syncthreads();

    // ---- Compute: thread = one co, TW pixels; inner loops over kh, ci ----
    float acc[TW];
    const float bv = __ldg(&bias[co]);
#pragma unroll
    for (int p = 0; p < TW; ++p) acc[p] = bv;

#pragma unroll
    for (int kh = 0; kh < 3; ++kh) {
        const float* srow_base = &smem[kh * SROW + g * CG];
        const float* wrow = &wgt[(kh * 3) * CG * C + co];
#pragma unroll 4
        for (int ci = 0; ci < CG; ++ci) {
            // weights for (kh, kw=0..2, ci, co): coalesced over lanes (co contiguous)
            const float wk0 = __ldg(&wrow[(0 * CG + ci) * C]);
            const float wk1 = __ldg(&wrow[(1 * CG + ci) * C]);
            const float wk2 = __ldg(&wrow[(2 * CG + ci) * C]);

            // input row for this (kh, ci): warp-uniform broadcast LDS
            const float* srow = srow_base + ci;
            float x[SCOLS];
#pragma unroll
            for (int c = 0; c < SCOLS; ++c) x[c] = srow[c * C];

#pragma unroll
            for (int p = 0; p < TW; ++p) {
                acc[p] = fmaf(x[p + 0], wk0, acc[p]);
                acc[p] = fmaf(x[p + 1], wk1, acc[p]);
                acc[p] = fmaf(x[p + 2], wk2, acc[p]);
            }
        }
    }

    // ---- Store: TW pixels, stride C over W dimension (coalesced over lanes) ----
    float* optr = &out[(((long)b * H + h) * W + w0) * C + co];
#pragma unroll
    for (int p = 0; p < TW; ++p) optr[p * C] = acc[p];
}

extern "C" void kernel_launch(void* const* d_in, const int* in_sizes, int n_in,
                              void* d_out, int out_size)
{
    const float* in   = (const float*)d_in[0];
    const float* wgt  = (const float*)d_in[1];
    const float* bias = (const float*)d_in[2];
    float* out = (float*)d_out;

    const int grid = B * H * TILES_W;  // 32*56*4 = 7168 blocks
    groupconv2d_kernel<<<grid, 256>>>(in, wgt, bias, out);
}

// round 3
// speedup vs baseline: 1.0394x; 1.0394x over previous
#include <cuda_runtime.h>
#include <cuda_bf16.h>

// GroupConv2D: B=32, H=W=56, Cin=Cout=256, G=8, 3x3 SAME, NHWC, HWIO weights, fp32.
// d_in[0] = inputs  [32,56,56,256] f32
// d_in[1] = kernel  [3,3,32,256]   f32  (HWIO, I = Cin/G = 32, O spans all 256)
// d_in[2] = bias    [256]          f32
// d_out   = output  [32,56,56,256] f32

namespace {
constexpr int B  = 32;
constexpr int H  = 56;
constexpr int W  = 56;
constexpr int C  = 256;   // Cin == Cout
constexpr int G  = 8;
constexpr int CG = C / G; // 32 channels per group
constexpr int TW = 14;    // output pixels per block along W
constexpr int TILES_W = W / TW;            // 4
constexpr int SCOLS = TW + 2;              // 16 (with halo)
constexpr int SROW  = SCOLS * C;           // 4096 floats per smem row
}

__global__ __launch_bounds__(256, 4)
void groupconv2d_kernel(const float* __restrict__ in,
                        const float* __restrict__ wgt,
                        const float* __restrict__ bias,
                        float* __restrict__ out)
{
    __shared__ __align__(16) float smem[3 * SCOLS * C];  // 48 KB

    const int tile = blockIdx.x;
    const int tw = tile % TILES_W;
    const int h  = (tile / TILES_W) % H;
    const int b  = tile / (TILES_W * H);
    const int w0 = tw * TW;

    const int co = threadIdx.x;       // output channel 0..255
    const int g  = co >> 5;           // group; warp-uniform

    // ---- Stage input tile (rows h-1..h+1, cols w0-1..w0+14, all 256 ch) ----
    for (int i = threadIdx.x; i < 3 * SCOLS * C / 4; i += 256) {
        const int idx = i * 4;
        const int ch4 = idx & (C - 1);
        const int col = (idx >> 8) & (SCOLS - 1);
        const int row = idx / SROW;
        const int hh = h + row - 1;
        const int ww = w0 + col - 1;
        float4 v = make_float4(0.f, 0.f, 0.f, 0.f);
        if (hh >= 0 && hh < H && ww >= 0 && ww < W) {
            v = *reinterpret_cast<const float4*>(
                    &in[(((long)b * H + hh) * W + ww) * C + ch4]);
        }
        reinterpret_cast<float4*>(smem)[i] = v;
    }
    __syncthreads();

    // ---- Compute: thread = one co, TW pixels ----
    float acc[TW];
    const float bv = __ldg(&bias[co]);
#pragma unroll
    for (int p = 0; p < TW; ++p) acc[p] = bv;

#pragma unroll
    for (int kh = 0; kh < 3; ++kh) {
        const float* srow = &smem[kh * SROW + g * CG];
        const float* wkh  = &wgt[(kh * 3) * CG * C + co];

#pragma unroll
        for (int cg = 0; cg < CG / 4; ++cg) {
            const int ci = cg * 4;

            // 12 weights for (kh, kw=0..2, ci..ci+3, co): coalesced over lanes
            float wk[3][4];
#pragma unroll
            for (int kw = 0; kw < 3; ++kw)
#pragma unroll
                for (int i = 0; i < 4; ++i)
                    wk[kw][i] = __ldg(&wkh[(kw * CG + ci + i) * C]);

            // rolling window of LDS.128 quads (4 consecutive ci) over 16 cols
            const float* sp = srow + ci;
            float4 q0 = *reinterpret_cast<const float4*>(sp + 0 * C);
            float4 q1 = *reinterpret_cast<const float4*>(sp + 1 * C);
#pragma unroll
            for (int p = 0; p < TW; ++p) {
                const float4 q2 = *reinterpret_cast<const float4*>(sp + (p + 2) * C);
                float a = acc[p];
                a = fmaf(q0.x, wk[0][0], a);
                a = fmaf(q0.y, wk[0][1], a);
                a = fmaf(q0.z, wk[0][2], a);
                a = fmaf(q0.w, wk[0][3], a);
                a = fmaf(q1.x, wk[1][0], a);
                a = fmaf(q1.y, wk[1][1], a);
                a = fmaf(q1.z, wk[1][2], a);
                a = fmaf(q1.w, wk[1][3], a);
                a = fmaf(q2.x, wk[2][0], a);
                a = fmaf(q2.y, wk[2][1], a);
                a = fmaf(q2.z, wk[2][2], a);
                a = fmaf(q2.w, wk[2][3], a);
                acc[p] = a;
                q0 = q1;
                q1 = q2;
            }
        }
    }

    // ---- Store: TW pixels, coalesced over lanes ----
    float* optr = &out[(((long)b * H + h) * W + w0) * C + co];
#pragma unroll
    for (int p = 0; p < TW; ++p) optr[p * C] = acc[p];
}

extern "C" void kernel_launch(void* const* d_in, const int* in_sizes, int n_in,
                              void* d_out, int out_size)
{
    const float* in   = (const float*)d_in[0];
    const float* wgt  = (const float*)d_in[1];
    const float* bias = (const float*)d_in[2];
    float* out = (float*)d_out;

    const int grid = B * H * TILES_W;  // 7168 blocks
    groupconv2d_kernel<<<grid, 256>>>(in, wgt, bias, out);
}

// round 4
// speedup vs baseline: 1.1484x; 1.1049x over previous
#include <cuda_runtime.h>
#include <cuda_bf16.h>
#include <cstdint>

// GroupConv2D: B=32, H=W=56, Cin=Cout=256, G=8, 3x3 SAME, NHWC, HWIO weights, fp32.
// Packed f32x2 FMA across input-channel pairs (Blackwell 2x fp32 path).

namespace {
constexpr int B  = 32;
constexpr int H  = 56;
constexpr int W  = 56;
constexpr int C  = 256;
constexpr int G  = 8;
constexpr int CG = C / G;     // 32
constexpr int TW = 14;
constexpr int TILES_W = W / TW;   // 4
constexpr int SCOLS = TW + 2;     // 16
constexpr int SROW  = SCOLS * C;  // 4096 floats
}

__device__ __forceinline__ uint64_t pack2(float lo, float hi) {
    uint64_t r;
    asm("mov.b64 %0, {%1, %2};" : "=l"(r) : "f"(lo), "f"(hi));
    return r;
}
__device__ __forceinline__ uint64_t fma2(uint64_t a, uint64_t b, uint64_t c) {
    uint64_t d;
    asm("fma.rn.f32x2 %0, %1, %2, %3;" : "=l"(d) : "l"(a), "l"(b), "l"(c));
    return d;
}
__device__ __forceinline__ float2 unpack2(uint64_t v) {
    float lo, hi;
    asm("mov.b64 {%0, %1}, %2;" : "=f"(lo), "=f"(hi) : "l"(v));
    return make_float2(lo, hi);
}

__global__ __launch_bounds__(256, 4)
void groupconv2d_kernel(const float* __restrict__ in,
                        const float* __restrict__ wgt,
                        const float* __restrict__ bias,
                        float* __restrict__ out)
{
    __shared__ __align__(16) float smem[3 * SCOLS * C];  // 48 KB

    const int tile = blockIdx.x;
    const int tw = tile % TILES_W;
    const int h  = (tile / TILES_W) % H;
    const int b  = tile / (TILES_W * H);
    const int w0 = tw * TW;

    const int co = threadIdx.x;     // output channel
    const int g  = co >> 5;         // group; warp-uniform

    // ---- Stage input tile (rows h-1..h+1, cols w0-1..w0+14, all 256 ch) ----
    for (int i = threadIdx.x; i < 3 * SCOLS * C / 4; i += 256) {
        const int idx = i * 4;
        const int ch4 = idx & (C - 1);
        const int col = (idx >> 8) & (SCOLS - 1);
        const int row = idx / SROW;
        const int hh = h + row - 1;
        const int ww = w0 + col - 1;
        float4 v = make_float4(0.f, 0.f, 0.f, 0.f);
        if (hh >= 0 && hh < H && ww >= 0 && ww < W) {
            v = *reinterpret_cast<const float4*>(
                    &in[(((long)b * H + hh) * W + ww) * C + ch4]);
        }
        reinterpret_cast<float4*>(smem)[i] = v;
    }
    __syncthreads();

    // ---- Compute: thread = one co, TW pixels; f32x2 across (ci, ci+1) ----
    // acc2[p] = (partial sum over even ci lanes, partial sum over odd ci lanes)
    uint64_t acc2[TW];
    const float bv = __ldg(&bias[co]);
#pragma unroll
    for (int p = 0; p < TW; ++p) acc2[p] = pack2(bv, 0.0f);

#pragma unroll
    for (int kh = 0; kh < 3; ++kh) {
        const float* srow = &smem[kh * SROW + g * CG];
        const float* wkh  = &wgt[(kh * 3) * CG * C + co];

#pragma unroll
        for (int cg = 0; cg < CG / 4; ++cg) {
            const int ci = cg * 4;

            // 12 weights (kh, kw=0..2, ci..ci+3, co) -> 6 packed pairs
            uint64_t wp[3][2];
#pragma unroll
            for (int kw = 0; kw < 3; ++kw) {
                const float a0 = __ldg(&wkh[(kw * CG + ci + 0) * C]);
                const float a1 = __ldg(&wkh[(kw * CG + ci + 1) * C]);
                const float a2 = __ldg(&wkh[(kw * CG + ci + 2) * C]);
                const float a3 = __ldg(&wkh[(kw * CG + ci + 3) * C]);
                wp[kw][0] = pack2(a0, a1);
                wp[kw][1] = pack2(a2, a3);
            }

            // rolling window of LDS.128 quads; each quad = two f32x2 operands
            const ulonglong2* sp =
                reinterpret_cast<const ulonglong2*>(srow + ci);
            // column stride in ulonglong2 units: C floats = C/4 ulonglong2... careful:
            // srow + ci + c*C floats; as ulonglong2*, stride = C/4? No: C floats = 1024B = 64 ulonglong2? 
            // ulonglong2 is 16B => C*4B/16B = C/4 elements.
            ulonglong2 q0 = sp[0 * (C / 4)];
            ulonglong2 q1 = sp[1 * (C / 4)];
#pragma unroll
            for (int p = 0; p < TW; ++p) {
                const ulonglong2 q2 = sp[(p + 2) * (C / 4)];
                uint64_t a = acc2[p];
                a = fma2(q0.x, wp[0][0], a);
                a = fma2(q0.y, wp[0][1], a);
                a = fma2(q1.x, wp[1][0], a);
                a = fma2(q1.y, wp[1][1], a);
                a = fma2(q2.x, wp[2][0], a);
                a = fma2(q2.y, wp[2][1], a);
                acc2[p] = a;
                q0 = q1;
                q1 = q2;
            }
        }
    }

    // ---- Reduce halves + store (coalesced over lanes) ----
    float* optr = &out[(((long)b * H + h) * W + w0) * C + co];
#pragma unroll
    for (int p = 0; p < TW; ++p) {
        const float2 v = unpack2(acc2[p]);
        optr[p * C] = v.x + v.y;
    }
}

extern "C" void kernel_launch(void* const* d_in, const int* in_sizes, int n_in,
                              void* d_out, int out_size)
{
    const float* in   = (const float*)d_in[0];
    const float* wgt  = (const float*)d_in[1];
    const float* bias = (const float*)d_in[2];
    float* out = (float*)d_out;

    const int grid = B * H * TILES_W;  // 7168 blocks
    groupconv2d_kernel<<<grid, 256>>>(in, wgt, bias, out);
}

// round 5
// speedup vs baseline: 2.8959x; 2.5216x over previous
#include <cuda_runtime.h>
#include <cuda_fp16.h>
#include <cstdint>

// GroupConv2D via warp-level fp16 HMMA (mma.sync.m16n8k16, f32 accum).
// Per group g: C[px, 32co] = A[px, K=288] x B[288, 32]  (implicit im2col).
// Block = (g, b, h): 128 threads = 4 warps = 4 m-tiles of 16 pixels.
// d_in[0]=inputs [32,56,56,256] f32, d_in[1]=kernel [3,3,32,256] f32,
// d_in[2]=bias [256] f32, d_out = [32,56,56,256] f32.

namespace {
constexpr int B = 32, H = 56, W = 56, C = 256, CG = 32;
constexpr int KH = 3;
constexpr int NCOL = 58;                       // cols: ww = -1..56
constexpr int IN_SM_BYTES = KH * NCOL * 64;    // 3*58 rows * 32ch*2B = 11136
constexpr int KTOT = 288;                      // 3*3*32
constexpr int W_SM_BYTES = KTOT * 64;          // 288 rows * 32n*2B = 18432
constexpr int NSTEP = KTOT / 16;               // 18 K-steps
}

__device__ __forceinline__ uint32_t smem_u32(const void* p) {
    return (uint32_t)__cvta_generic_to_shared(p);
}

__device__ __forceinline__ uint4 cvt8_f32_to_f16(float4 v0, float4 v1) {
    __half2 h0 = __floats2half2_rn(v0.x, v0.y);
    __half2 h1 = __floats2half2_rn(v0.z, v0.w);
    __half2 h2 = __floats2half2_rn(v1.x, v1.y);
    __half2 h3 = __floats2half2_rn(v1.z, v1.w);
    uint4 r;
    r.x = *reinterpret_cast<uint32_t*>(&h0);
    r.y = *reinterpret_cast<uint32_t*>(&h1);
    r.z = *reinterpret_cast<uint32_t*>(&h2);
    r.w = *reinterpret_cast<uint32_t*>(&h3);
    return r;
}

__global__ __launch_bounds__(128, 7)
void groupconv_hmma(const float* __restrict__ in,
                    const float* __restrict__ wgt,
                    const float* __restrict__ bias,
                    float* __restrict__ out)
{
    __shared__ __align__(16) unsigned char in_sm[IN_SM_BYTES];
    __shared__ __align__(16) unsigned char w_sm[W_SM_BYTES];

    const int bid = blockIdx.x;
    const int g = bid & 7;
    const int h = (bid >> 3) % H;
    const int b = bid / (8 * H);

    const int tid  = threadIdx.x;
    const int lane = tid & 31;
    const int mt   = tid >> 5;      // warp = m-tile (16 pixels)
    const int w0   = mt * 16;

    // ---- Stage input slice: rows h-1..h+1, cols -1..56, this group's 32 ch.
    // chunk = (kh, col, j8): 8 halves (16B) per chunk; swizzle gran = j8 ^ ((col>>1)&3)
    for (int cid = tid; cid < KH * NCOL * 4; cid += 128) {
        const int kh  = cid / (NCOL * 4);
        const int rem = cid - kh * (NCOL * 4);
        const int col = rem >> 2;
        const int j8  = rem & 3;
        const int hh = h + kh - 1;
        const int ww = col - 1;
        uint4 st = make_uint4(0u, 0u, 0u, 0u);
        if (hh >= 0 && hh < H && ww >= 0 && ww < W) {
            const float4* src = reinterpret_cast<const float4*>(
                &in[(((long)b * H + hh) * W + ww) * C + g * CG + j8 * 8]);
            st = cvt8_f32_to_f16(src[0], src[1]);
        }
        const int gran = j8 ^ ((col >> 1) & 3);
        *reinterpret_cast<uint4*>(&in_sm[(kh * NCOL + col) * 64 + gran * 16]) = st;
    }

    // ---- Stage weights: B[k=288][n=32] fp16, swizzle gran = nt ^ ((k>>1)&3)
    for (int cid = tid; cid < KTOT * 4; cid += 128) {
        const int k  = cid >> 2;
        const int nt = cid & 3;
        const float4* src = reinterpret_cast<const float4*>(
            &wgt[(long)k * C + g * CG + nt * 8]);
        uint4 st = cvt8_f32_to_f16(src[0], src[1]);
        const int gran = nt ^ ((k >> 1) & 3);
        *reinterpret_cast<uint4*>(&w_sm[k * 64 + gran * 16]) = st;
    }
    __syncthreads();

    // ---- Lane geometry for ldmatrix ----
    // A (x4): lanes 0-15 -> pixel p=lane, k-half 0; lanes 16-31 -> p=lane-16, k-half 8
    const int p     = lane & 15;
    const int koff8 = (lane >> 4) << 3;   // 0 or 8
    const int wpix  = w0 + p;
    int cbase[3], csel[3];
#pragma unroll
    for (int kw = 0; kw < 3; ++kw) {
        int c = wpix + kw;                 // col index for (w, kw); col0 == ww=-1
        if (c > NCOL - 1) c = NCOL - 1;    // clamp padded pixels (masked at store)
        cbase[kw] = c * 64;
        csel[kw]  = (c >> 1) & 3;
    }
    const uint32_t in_base = smem_u32(in_sm);
    const uint32_t w_base  = smem_u32(w_sm);

    // B (x2.trans): lanes 0-15 -> row k = s*16 + li
    const int li = lane & 15;
    const uint32_t bB = w_base + li * 64;
    const int kx = (li >> 1) & 3;          // == ((s*16+li)>>1)&3 since s*8 % 4 == 0
    uint32_t ntoff[4];
#pragma unroll
    for (int nt = 0; nt < 4; ++nt) ntoff[nt] = (uint32_t)((nt ^ kx) * 16);

    float acc[4][4];
#pragma unroll
    for (int nt = 0; nt < 4; ++nt)
#pragma unroll
        for (int i = 0; i < 4; ++i) acc[nt][i] = 0.f;

    // ---- Main loop: 18 K-steps, s = (kh*3 + kw)*2 + cih ----
#pragma unroll
    for (int s = 0; s < NSTEP; ++s) {
        const int kh  = s / 6;
        const int kw  = (s / 2) % 3;
        const int cih = s & 1;
        const int ch0 = cih * 16 + koff8;          // 0,8,16,24
        const int j   = ch0 >> 3;

        uint32_t a_addr = in_base + (uint32_t)(kh * NCOL * 64)
                        + (uint32_t)cbase[kw]
                        + (uint32_t)((j ^ csel[kw]) * 16);
        uint32_t a0, a1, a2, a3;
        asm volatile(
            "ldmatrix.sync.aligned.m8n8.x4.shared.b16 {%0,%1,%2,%3}, [%4];"
            : "=r"(a0), "=r"(a1), "=r"(a2), "=r"(a3) : "r"(a_addr));

        const uint32_t bbase_s = bB + (uint32_t)(s * 1024);
#pragma unroll
        for (int nt = 0; nt < 4; ++nt) {
            uint32_t b0, b1;
            asm volatile(
                "ldmatrix.sync.aligned.m8n8.x2.trans.shared.b16 {%0,%1}, [%2];"
                : "=r"(b0), "=r"(b1) : "r"(bbase_s + ntoff[nt]));
            asm volatile(
                "mma.sync.aligned.m16n8k16.row.col.f32.f16.f16.f32 "
                "{%0,%1,%2,%3}, {%4,%5,%6,%7}, {%8,%9}, {%0,%1,%2,%3};"
                : "+f"(acc[nt][0]), "+f"(acc[nt][1]),
                  "+f"(acc[nt][2]), "+f"(acc[nt][3])
                : "r"(a0), "r"(a1), "r"(a2), "r"(a3), "r"(b0), "r"(b1));
        }
    }

    // ---- Epilogue: C frag thread mapping: rows lane>>2 (+8), cols 2*(lane&3)+{0,1}
    const int r0 = lane >> 2;
    const int n2 = (lane & 3) * 2;
    const long outrow = ((long)b * H + h) * W;
#pragma unroll
    for (int nt = 0; nt < 4; ++nt) {
        const int co = g * CG + nt * 8 + n2;
        const float2 bv = *reinterpret_cast<const float2*>(&bias[co]);
        const int w1 = w0 + r0;
        if (w1 < W) {
            float2 o = make_float2(acc[nt][0] + bv.x, acc[nt][1] + bv.y);
            *reinterpret_cast<float2*>(&out[(outrow + w1) * C + co]) = o;
        }
        const int w2 = w0 + r0 + 8;
        if (w2 < W) {
            float2 o = make_float2(acc[nt][2] + bv.x, acc[nt][3] + bv.y);
            *reinterpret_cast<float2*>(&out[(outrow + w2) * C + co]) = o;
        }
    }
}

extern "C" void kernel_launch(void* const* d_in, const int* in_sizes, int n_in,
                              void* d_out, int out_size)
{
    const float* in   = (const float*)d_in[0];
    const float* wgt  = (const float*)d_in[1];
    const float* bias = (const float*)d_in[2];
    float* out = (float*)d_out;

    const int grid = 8 * H * B;   // group x h x batch = 14336 blocks
    groupconv_hmma<<<grid, 128>>>(in, wgt, bias, out);
}

// round 7
// speedup vs baseline: 4.8644x; 1.6797x over previous
#include <cuda_runtime.h>
#include <cuda_fp16.h>
#include <cstdint>

// GroupConv2D via warp-level fp16 HMMA (mma.sync.m16n8k16, f32 accum).
// Block = (g, b, 4-row band): 224 px = 14 m-tiles; 7 warps x 2 m-tiles.
// B operand loaded with ldmatrix.x4.trans (2 n-tiles per op), amortized over
// 2 m-tiles per warp; weights staged once per 4 output rows.
// d_in[0]=inputs [32,56,56,256] f32, d_in[1]=kernel [3,3,32,256] f32,
// d_in[2]=bias [256] f32, d_out = [32,56,56,256] f32.
//
// (Re-submission of R5 design: previous round died with
//  "system not yet initialized" in harness init — infra, kernel never ran.)

namespace {
constexpr int B = 32, H = 56, W = 56, C = 256, CG = 32;
constexpr int ROWS = 4;                      // output rows per block
constexpr int IN_ROWS = ROWS + 2;            // 6 staged input rows
constexpr int NCOL = 58;                     // cols: ww = -1..56
constexpr int IN_SM_BYTES = IN_ROWS * NCOL * 64;   // 22272
constexpr int KTOT = 288;                    // 3*3*32
constexpr int W_SM_BYTES = KTOT * 64;        // 18432
constexpr int NSTEP = KTOT / 16;             // 18
constexpr int THREADS = 224;                 // 7 warps
}

__device__ __forceinline__ uint32_t smem_u32(const void* p) {
    return (uint32_t)__cvta_generic_to_shared(p);
}

__device__ __forceinline__ uint4 cvt8_f32_to_f16(float4 v0, float4 v1) {
    __half2 h0 = __floats2half2_rn(v0.x, v0.y);
    __half2 h1 = __floats2half2_rn(v0.z, v0.w);
    __half2 h2 = __floats2half2_rn(v1.x, v1.y);
    __half2 h3 = __floats2half2_rn(v1.z, v1.w);
    uint4 r;
    r.x = *reinterpret_cast<uint32_t*>(&h0);
    r.y = *reinterpret_cast<uint32_t*>(&h1);
    r.z = *reinterpret_cast<uint32_t*>(&h2);
    r.w = *reinterpret_cast<uint32_t*>(&h3);
    return r;
}

__global__ __launch_bounds__(THREADS, 4)
void groupconv_hmma(const float* __restrict__ in,
                    const float* __restrict__ wgt,
                    const float* __restrict__ bias,
                    float* __restrict__ out)
{
    __shared__ __align__(16) unsigned char in_sm[IN_SM_BYTES];
    __shared__ __align__(16) unsigned char w_sm[W_SM_BYTES];

    const int bid = blockIdx.x;
    const int g  = bid & 7;
    const int hq = (bid >> 3) % (H / ROWS);   // 0..13
    const int b  = bid / (8 * (H / ROWS));
    const int h0 = hq * ROWS;

    const int tid  = threadIdx.x;
    const int lane = tid & 31;
    const int warp = tid >> 5;                // 0..6

    // ---- Stage input: rows h0-1..h0+4, cols -1..56, this group's 32 ch ----
    for (int cid = tid; cid < IN_ROWS * NCOL * 4; cid += THREADS) {
        const int r   = cid / (NCOL * 4);
        const int rem = cid - r * (NCOL * 4);
        const int col = rem >> 2;
        const int j8  = rem & 3;
        const int hh = h0 - 1 + r;
        const int ww = col - 1;
        uint4 st = make_uint4(0u, 0u, 0u, 0u);
        if (hh >= 0 && hh < H && ww >= 0 && ww < W) {
            const float4* src = reinterpret_cast<const float4*>(
                &in[(((long)b * H + hh) * W + ww) * C + g * CG + j8 * 8]);
            st = cvt8_f32_to_f16(src[0], src[1]);
        }
        const int gran = j8 ^ ((col >> 1) & 3);
        *reinterpret_cast<uint4*>(&in_sm[(r * NCOL + col) * 64 + gran * 16]) = st;
    }

    // ---- Stage weights: B[k=288][n=32] fp16, gran = nt ^ ((k>>1)&3) ----
    for (int cid = tid; cid < KTOT * 4; cid += THREADS) {
        const int k  = cid >> 2;
        const int nt = cid & 3;
        const float4* src = reinterpret_cast<const float4*>(
            &wgt[(long)k * C + g * CG + nt * 8]);
        uint4 st = cvt8_f32_to_f16(src[0], src[1]);
        const int gran = nt ^ ((k >> 1) & 3);
        *reinterpret_cast<uint4*>(&w_sm[k * 64 + gran * 16]) = st;
    }
    __syncthreads();

    const uint32_t in_base = smem_u32(in_sm);
    const uint32_t w_base  = smem_u32(w_sm);

    // ---- A lane geometry: 2 m-tiles per warp, 16 linear pixels each ----
    // px -> (hrow = px/56, wcol = px%56); lanes 16-31 take k-half +8.
    const int q = lane >> 4;                  // 0/1 = k-half select
    int colpart[2][3];                        // ((hr*58)+wc+kw)*64
    int csel[2][3];
#pragma unroll
    for (int t = 0; t < 2; ++t) {
        const int px = (warp * 2 + t) * 16 + (lane & 15);
        const int hr = px / W;
        const int wc = px - hr * W;
#pragma unroll
        for (int kw = 0; kw < 3; ++kw) {
            const int c = wc + kw;            // 0..57
            colpart[t][kw] = (hr * NCOL + c) * 64;
            csel[t][kw]    = (c >> 1) & 3;
        }
    }

    // ---- B lane geometry: ldmatrix.x4.trans, 2 n-tiles per op ----
    // lanes 0-15 -> n-tile ntp*2, lanes 16-31 -> ntp*2+1; row k = s*16 + li.
    const int li = lane & 15;
    const int kx = (li >> 1) & 3;
    uint32_t boff[2];
#pragma unroll
    for (int ntp = 0; ntp < 2; ++ntp)
        boff[ntp] = (uint32_t)(li * 64 + (((ntp * 2 + q) ^ kx) * 16));

    float acc[2][4][4];
#pragma unroll
    for (int t = 0; t < 2; ++t)
#pragma unroll
        for (int nt = 0; nt < 4; ++nt)
#pragma unroll
            for (int i = 0; i < 4; ++i) acc[t][nt][i] = 0.f;

    // ---- Main loop: s = (kh*3 + kw)*2 + cih ----
#pragma unroll
    for (int s = 0; s < NSTEP; ++s) {
        const int kh  = s / 6;
        const int kw  = (s / 2) % 3;
        const int cih = s & 1;
        const int j   = cih * 2 + q;          // 16B granule of this k-half

        uint32_t a[2][4];
#pragma unroll
        for (int t = 0; t < 2; ++t) {
            const uint32_t a_addr = in_base
                + (uint32_t)(colpart[t][kw] + kh * (NCOL * 64))
                + (uint32_t)((j ^ csel[t][kw]) << 4);
            asm volatile(
                "ldmatrix.sync.aligned.m8n8.x4.shared.b16 {%0,%1,%2,%3}, [%4];"
                : "=r"(a[t][0]), "=r"(a[t][1]), "=r"(a[t][2]), "=r"(a[t][3])
                : "r"(a_addr));
        }

        uint32_t bf[2][4];
        const uint32_t bb = w_base + (uint32_t)(s * 1024);
#pragma unroll
        for (int ntp = 0; ntp < 2; ++ntp) {
            asm volatile(
                "ldmatrix.sync.aligned.m8n8.x4.trans.shared.b16 {%0,%1,%2,%3}, [%4];"
                : "=r"(bf[ntp][0]), "=r"(bf[ntp][1]),
                  "=r"(bf[ntp][2]), "=r"(bf[ntp][3])
                : "r"(bb + boff[ntp]));
        }

#pragma unroll
        for (int t = 0; t < 2; ++t)
#pragma unroll
            for (int nt = 0; nt < 4; ++nt) {
                const uint32_t b0 = bf[nt >> 1][(nt & 1) * 2 + 0];
                const uint32_t b1 = bf[nt >> 1][(nt & 1) * 2 + 1];
                asm volatile(
                    "mma.sync.aligned.m16n8k16.row.col.f32.f16.f16.f32 "
                    "{%0,%1,%2,%3}, {%4,%5,%6,%7}, {%8,%9}, {%0,%1,%2,%3};"
                    : "+f"(acc[t][nt][0]), "+f"(acc[t][nt][1]),
                      "+f"(acc[t][nt][2]), "+f"(acc[t][nt][3])
                    : "r"(a[t][0]), "r"(a[t][1]), "r"(a[t][2]), "r"(a[t][3]),
                      "r"(b0), "r"(b1));
            }
    }

    // ---- Epilogue: C rows lane>>2 (+8), cols 2*(lane&3)+{0,1}; all px valid ----
    const int r0 = lane >> 2;
    const int n2 = (lane & 3) * 2;
    const long base_off = ((long)b * H + h0) * W;   // h0 row base (pixel units)
#pragma unroll
    for (int t = 0; t < 2; ++t) {
        const int pxb = (warp * 2 + t) * 16;
#pragma unroll
        for (int half = 0; half < 2; ++half) {
            const int px = pxb + r0 + half * 8;
            const int hr = px / W;
            const int wc = px - hr * W;
            const long po = (base_off + (long)hr * W + wc) * C;
#pragma unroll
            for (int nt = 0; nt < 4; ++nt) {
                const int co = g * CG + nt * 8 + n2;
                const float2 bv = *reinterpret_cast<const float2*>(&bias[co]);
                float2 o = make_float2(acc[t][nt][half * 2 + 0] + bv.x,
                                       acc[t][nt][half * 2 + 1] + bv.y);
                *reinterpret_cast<float2*>(&out[po + co]) = o;
            }
        }
    }
}

extern "C" void kernel_launch(void* const* d_in, const int* in_sizes, int n_in,
                              void* d_out, int out_size)
{
    const float* in   = (const float*)d_in[0];
    const float* wgt  = (const float*)d_in[1];
    const float* bias = (const float*)d_in[2];
    float* out = (float*)d_out;

    const int grid = 8 * (H / ROWS) * B;   // 8 * 14 * 32 = 3584 blocks
    groupconv_hmma<<<grid, THREADS>>>(in, wgt, bias, out);
}